// round 1
// baseline (speedup 1.0000x reference)
#include <cuda_runtime.h>
#include <math.h>

#define D_MODEL 1024
#define NH 16
#define DK 64
#define BATCH 2
#define LSEQ 2048
#define MTOT (BATCH*LSEQ)   // 4096

// Scratch (allocation-free rule: __device__ globals)
__device__ float g_qh[(size_t)BATCH*NH*LSEQ*DK];   // [B,H,L,Dk]
__device__ float g_kh[(size_t)BATCH*NH*LSEQ*DK];
__device__ float g_vh[(size_t)BATCH*NH*LSEQ*DK];
__device__ float g_att[(size_t)MTOT*D_MODEL];      // [B*L, D]

// ---------------------------------------------------------------------------
// C = A(M x 1024) @ W(1024 x 1024) + bias
// MODE 0: write into head layout [B,H,L,Dk]; MODE 1: row-major [M,N]
// BM=BN=128, BK=16, 256 threads, 8x8 per-thread tile
// ---------------------------------------------------------------------------
template<int MODE>
__global__ __launch_bounds__(256) void gemm128(const float* __restrict__ A,
                                               const float* __restrict__ W,
                                               const float* __restrict__ bias,
                                               float* __restrict__ C) {
    const int Kdim = D_MODEL, Ndim = D_MODEL;
    __shared__ float As[16*132];   // A^T tile: As[k][m], padded stride 132
    __shared__ float Ws[16*128];   // Ws[k][n]
    const int m0 = blockIdx.y * 128, n0 = blockIdx.x * 128;
    const int t = threadIdx.x;
    const int tx = t & 15, ty = t >> 4;
    float acc[8][8] = {};

    for (int k0 = 0; k0 < Kdim; k0 += 16) {
        #pragma unroll
        for (int it = 0; it < 2; it++) {
            int f = t + it * 256;
            int row = f >> 2, kq = (f & 3) * 4;
            float4 v = *(const float4*)(A + (size_t)(m0 + row) * Kdim + k0 + kq);
            As[(kq + 0) * 132 + row] = v.x;
            As[(kq + 1) * 132 + row] = v.y;
            As[(kq + 2) * 132 + row] = v.z;
            As[(kq + 3) * 132 + row] = v.w;
        }
        #pragma unroll
        for (int it = 0; it < 2; it++) {
            int f = t + it * 256;
            int kr = f >> 5, nq = (f & 31) * 4;
            *(float4*)(Ws + kr * 128 + nq) =
                *(const float4*)(W + (size_t)(k0 + kr) * Ndim + n0 + nq);
        }
        __syncthreads();
        #pragma unroll
        for (int k = 0; k < 16; k++) {
            float a[8], b[8];
            *(float4*)(a)     = *(float4*)(As + k * 132 + ty * 8);
            *(float4*)(a + 4) = *(float4*)(As + k * 132 + ty * 8 + 4);
            *(float4*)(b)     = *(float4*)(Ws + k * 128 + tx * 8);
            *(float4*)(b + 4) = *(float4*)(Ws + k * 128 + tx * 8 + 4);
            #pragma unroll
            for (int i = 0; i < 8; i++)
                #pragma unroll
                for (int j = 0; j < 8; j++)
                    acc[i][j] += a[i] * b[j];
        }
        __syncthreads();
    }

    #pragma unroll
    for (int i = 0; i < 8; i++) {
        int m = m0 + ty * 8 + i;
        #pragma unroll
        for (int j = 0; j < 8; j++) {
            int n = n0 + tx * 8 + j;
            float v = acc[i][j] + bias[n];
            if (MODE == 0) {
                int b = m >> 11, l = m & (LSEQ - 1);
                int h = n >> 6,  d = n & (DK - 1);
                C[(((size_t)(b * NH + h)) * LSEQ + l) * DK + d] = v;
            } else {
                C[(size_t)m * Ndim + n] = v;
            }
        }
    }
}

// ---------------------------------------------------------------------------
// Flash attention, fp32. Per block: one (b,h) and 64 query rows.
// Br=Bc=64, Dk=64; 256 threads; thread (rg=t/16, cg=t%16) owns 4 rows x 4 cols.
// Output written into [B,L,D] layout for the final projection GEMM.
// ---------------------------------------------------------------------------
#define ATS 68                       // padded row stride
#define ATT_SMEM (4*64*ATS*4)        // Qs,Ks,Vs,Ps

__global__ __launch_bounds__(256) void attn64(const float* __restrict__ Q,
                                              const float* __restrict__ K,
                                              const float* __restrict__ V,
                                              float* __restrict__ O) {
    extern __shared__ float sm[];
    float* Qs = sm;
    float* Ks = Qs + 64 * ATS;
    float* Vs = Ks + 64 * ATS;
    float* Ps = Vs + 64 * ATS;

    const int bh = blockIdx.y;              // 0..B*H-1
    const int q0 = blockIdx.x * 64;
    const float* Qb = Q + (size_t)bh * LSEQ * DK;
    const float* Kb = K + (size_t)bh * LSEQ * DK;
    const float* Vb = V + (size_t)bh * LSEQ * DK;
    const int t = threadIdx.x;

    // Load Q tile (64x64)
    for (int f = t; f < 64 * 16; f += 256) {
        int r = f >> 4, c = (f & 15) * 4;
        *(float4*)(Qs + r * ATS + c) = *(const float4*)(Qb + (size_t)(q0 + r) * DK + c);
    }

    const int rg = t >> 4, cg = t & 15;
    float mi[4], li[4], o[4][4];
    #pragma unroll
    for (int i = 0; i < 4; i++) {
        mi[i] = -1e30f; li[i] = 0.f;
        #pragma unroll
        for (int j = 0; j < 4; j++) o[i][j] = 0.f;
    }

    for (int kt = 0; kt < LSEQ / 64; kt++) {
        __syncthreads();                    // previous P@V done (and Q load on iter 0)
        const int k0 = kt * 64;
        for (int f = t; f < 64 * 16; f += 256) {
            int r = f >> 4, c = (f & 15) * 4;
            *(float4*)(Ks + r * ATS + c) = *(const float4*)(Kb + (size_t)(k0 + r) * DK + c);
            *(float4*)(Vs + r * ATS + c) = *(const float4*)(Vb + (size_t)(k0 + r) * DK + c);
        }
        __syncthreads();

        // S = Q K^T / 8
        float s[4][4] = {};
        #pragma unroll 8
        for (int d = 0; d < 64; d++) {
            float qv[4], kv[4];
            #pragma unroll
            for (int i = 0; i < 4; i++) qv[i] = Qs[(rg * 4 + i) * ATS + d];
            #pragma unroll
            for (int j = 0; j < 4; j++) kv[j] = Ks[(cg * 4 + j) * ATS + d];
            #pragma unroll
            for (int i = 0; i < 4; i++)
                #pragma unroll
                for (int j = 0; j < 4; j++)
                    s[i][j] += qv[i] * kv[j];
        }

        float rmax[4];
        #pragma unroll
        for (int i = 0; i < 4; i++) {
            float mx = -1e30f;
            #pragma unroll
            for (int j = 0; j < 4; j++) { s[i][j] *= 0.125f; mx = fmaxf(mx, s[i][j]); }
            rmax[i] = mx;
        }
        #pragma unroll
        for (int msk = 1; msk < 16; msk <<= 1)
            #pragma unroll
            for (int i = 0; i < 4; i++)
                rmax[i] = fmaxf(rmax[i], __shfl_xor_sync(0xffffffffu, rmax[i], msk));

        float alpha[4], rsum[4];
        #pragma unroll
        for (int i = 0; i < 4; i++) {
            float mn = fmaxf(mi[i], rmax[i]);
            alpha[i] = __expf(mi[i] - mn);
            mi[i] = mn;
            float rs = 0.f;
            #pragma unroll
            for (int j = 0; j < 4; j++) {
                float p = __expf(s[i][j] - mn);
                Ps[(rg * 4 + i) * ATS + cg * 4 + j] = p;
                rs += p;
            }
            rsum[i] = rs;
        }
        #pragma unroll
        for (int msk = 1; msk < 16; msk <<= 1)
            #pragma unroll
            for (int i = 0; i < 4; i++)
                rsum[i] += __shfl_xor_sync(0xffffffffu, rsum[i], msk);
        #pragma unroll
        for (int i = 0; i < 4; i++) {
            li[i] = li[i] * alpha[i] + rsum[i];
            #pragma unroll
            for (int j = 0; j < 4; j++) o[i][j] *= alpha[i];
        }
        __syncthreads();                    // P visible

        // O += P @ V
        #pragma unroll 4
        for (int c = 0; c < 64; c++) {
            float4 vv = *(float4*)(Vs + c * ATS + cg * 4);
            #pragma unroll
            for (int i = 0; i < 4; i++) {
                float p = Ps[(rg * 4 + i) * ATS + c];
                o[i][0] += p * vv.x; o[i][1] += p * vv.y;
                o[i][2] += p * vv.z; o[i][3] += p * vv.w;
            }
        }
    }

    // epilogue: normalize, write to [B,L,D]
    const int b = bh >> 4, h = bh & 15;
    #pragma unroll
    for (int i = 0; i < 4; i++) {
        float inv = 1.f / li[i];
        int m = q0 + rg * 4 + i;
        float4 r;
        r.x = o[i][0] * inv; r.y = o[i][1] * inv;
        r.z = o[i][2] * inv; r.w = o[i][3] * inv;
        *(float4*)(O + ((size_t)(b * LSEQ + m)) * D_MODEL + h * DK + cg * 4) = r;
    }
}

// ---------------------------------------------------------------------------
extern "C" void kernel_launch(void* const* d_in, const int* in_sizes, int n_in,
                              void* d_out, int out_size) {
    const float* q  = (const float*)d_in[0];
    const float* k  = (const float*)d_in[1];
    const float* v  = (const float*)d_in[2];
    const float* Wq = (const float*)d_in[3];
    const float* bq = (const float*)d_in[4];
    const float* Wk = (const float*)d_in[5];
    const float* bk = (const float*)d_in[6];
    const float* Wv = (const float*)d_in[7];
    const float* bv = (const float*)d_in[8];
    const float* Wo = (const float*)d_in[9];
    const float* bo = (const float*)d_in[10];
    float* out = (float*)d_out;

    float *qh, *kh, *vh, *att;
    cudaGetSymbolAddress((void**)&qh,  g_qh);
    cudaGetSymbolAddress((void**)&kh,  g_kh);
    cudaGetSymbolAddress((void**)&vh,  g_vh);
    cudaGetSymbolAddress((void**)&att, g_att);

    static bool attr_set = false;
    if (!attr_set) {
        cudaFuncSetAttribute(attn64, cudaFuncAttributeMaxDynamicSharedMemorySize, ATT_SMEM);
        attr_set = true;
    }

    dim3 ggrid(D_MODEL / 128, MTOT / 128);   // (8, 32)
    gemm128<0><<<ggrid, 256>>>(q, Wq, bq, qh);
    gemm128<0><<<ggrid, 256>>>(k, Wk, bk, kh);
    gemm128<0><<<ggrid, 256>>>(v, Wv, bv, vh);

    dim3 agrid(LSEQ / 64, BATCH * NH);       // (32, 32)
    attn64<<<agrid, 256, ATT_SMEM>>>(qh, kh, vh, att);

    gemm128<1><<<ggrid, 256>>>(att, Wo, bo, out);
}